// round 15
// baseline (speedup 1.0000x reference)
#include <cuda_runtime.h>
#include <cstdint>

// 7x7 single-out-channel conv via mma.sync tf32 implicit GEMM.
// Round 15: R12's guard-free steady-state chunks (alu win) combined with
// R11's 4-warp non-blocking epilogue (12/16 warps continue into the next
// row's loads while 4 warps reduce). BAND=64, one wave (128 CTAs),
// 512 threads = 8 m-tiles x 2 k-halves, B fragments register-resident.

#define HW 128
#define HW2 (HW * HW)
#define C_DIM 64
#define BAND 64
#define NT 512

static __device__ __forceinline__ uint32_t f2tf(float v) {
    uint32_t r;
    asm("cvt.rna.tf32.f32 %0, %1;" : "=r"(r) : "f"(v));
    return r;
}

static __device__ __forceinline__ void mma8(float (&d)[4], const uint32_t (&a)[4],
                                            uint32_t b0, uint32_t b1) {
    asm("mma.sync.aligned.m16n8k8.row.col.f32.tf32.tf32.f32 "
        "{%0,%1,%2,%3}, {%4,%5,%6,%7}, {%8,%9}, {%0,%1,%2,%3};"
        : "+f"(d[0]), "+f"(d[1]), "+f"(d[2]), "+f"(d[3])
        : "r"(a[0]), "r"(a[1]), "r"(a[2]), "r"(a[3]), "r"(b0), "r"(b1));
}

__global__ void __launch_bounds__(NT, 1)
conv7x7_r15(const float* __restrict__ x, const float* __restrict__ w,
            const float* __restrict__ bias, float* __restrict__ out)
{
    // partial D: [buffer][kp][pixel][dw, pitch 10 for float2-aligned STS]
    __shared__ __align__(16) float s_part[2][2][HW][10];

    const int tid  = threadIdx.x;
    const int wid  = tid >> 5;
    const int lane = tid & 31;
    const int g    = lane >> 2;       // pixel-within-tile row / n-index
    const int q    = lane & 3;        // k-quad
    const int t    = wid & 7;         // m-tile (16 pixels)
    const int kp   = wid >> 3;        // channel half: kp*32 .. kp*32+31
    const int pb   = t * 16 + g;      // thread's pixel rows: pb, pb+8

    const int b      = blockIdx.y;
    const int ostart = blockIdx.x * BAND;
    const int oend   = ostart + BAND;
    const int rlo    = (ostart - 3 < 0) ? 0 : ostart - 3;
    const int rhi    = (oend + 2 > HW - 1) ? HW - 1 : oend + 2;

    // ---- B fragments resident in registers ----
    uint32_t bw[7][4][2];
#pragma unroll
    for (int dh = 0; dh < 7; ++dh)
#pragma unroll
        for (int i = 0; i < 4; ++i) {
            const int c = (kp * 4 + i) * 8 + 2 * q;
            bw[dh][i][0] = (g < 7) ? f2tf(w[c * 49 + dh * 7 + g]) : 0u;
            bw[dh][i][1] = (g < 7) ? f2tf(w[(c + 1) * 49 + dh * 7 + g]) : 0u;
        }

    float* outb = out + (size_t)b * HW2;
    const float bv = bias[0];

    float acc[7][4];
#pragma unroll
    for (int j = 0; j < 7; ++j)
#pragma unroll
        for (int k2 = 0; k2 < 4; ++k2) acc[j][k2] = 0.f;

    // single A pointer; k-step blocks reached via immediate offsets
    const float* pA = x + (size_t)b * C_DIM * HW2
                        + (size_t)(kp * 32 + 2 * q) * HW2 + pb + (size_t)rlo * HW;

    uint32_t av[4][4];
#pragma unroll
    for (int i = 0; i < 4; ++i) {
        const float* p = pA + i * 8 * HW2;
        av[i][0] = __float_as_uint(p[0]);
        av[i][1] = __float_as_uint(p[8]);
        av[i][2] = __float_as_uint(p[HW2]);
        av[i][3] = __float_as_uint(p[HW2 + 8]);
    }
    pA += HW;   // points at row rlo+1

    int epar = 0;
    int r = rlo;

#define PHASE(P, G)                                                           \
    {                                                                         \
        if (!(G) || r <= rhi) {                                               \
            _Pragma("unroll") for (int i_ = 0; i_ < 4; ++i_) {                \
                uint32_t tmp_[4];                                             \
                _Pragma("unroll") for (int k_ = 0; k_ < 4; ++k_)              \
                    tmp_[k_] = f2tf(__uint_as_float(av[i_][k_]));             \
                if (!(G) || r < rhi) {                                        \
                    const float* p_ = pA + i_ * 8 * HW2;                      \
                    av[i_][0] = __float_as_uint(p_[0]);                       \
                    av[i_][1] = __float_as_uint(p_[8]);                       \
                    av[i_][2] = __float_as_uint(p_[HW2]);                     \
                    av[i_][3] = __float_as_uint(p_[HW2 + 8]);                 \
                }                                                             \
                _Pragma("unroll") for (int j_ = 0; j_ < 7; ++j_) {            \
                    const int o_ = r - 3 + j_;                                \
                    if (!(G) || (o_ >= ostart && o_ < oend))                  \
                        mma8(acc[((P) + j_) % 7], tmp_,                       \
                             bw[6 - j_][i_][0], bw[6 - j_][i_][1]);           \
                }                                                             \
            }                                                                 \
            pA += HW;                                                         \
        }                                                                     \
        const int o0_ = r - 3;                                                \
        if (!(G) || (o0_ >= ostart && o0_ < oend)) {                          \
            float (&A_)[4] = acc[(P) % 7];                                    \
            *reinterpret_cast<float2*>(&s_part[epar][kp][pb][2 * q]) =        \
                make_float2(A_[0], A_[1]);                                    \
            *reinterpret_cast<float2*>(&s_part[epar][kp][pb + 8][2 * q]) =    \
                make_float2(A_[2], A_[3]);                                    \
            __syncthreads();                                                  \
            if (tid < HW) {                                                   \
                float s_ = bv;                                                \
                _Pragma("unroll") for (int dw_ = 0; dw_ < 7; ++dw_) {         \
                    const int p_ = tid + dw_ - 3;                             \
                    if ((unsigned)p_ < (unsigned)HW)                          \
                        s_ += s_part[epar][0][p_][dw_]                        \
                            + s_part[epar][1][p_][dw_];                       \
                }                                                             \
                outb[o0_ * HW + tid] = s_;                                    \
            }                                                                 \
            _Pragma("unroll") for (int k_ = 0; k_ < 4; ++k_)                  \
                A_[k_] = 0.f;                                                 \
            epar ^= 1;                                                        \
        }                                                                     \
        ++r;                                                                  \
    }

#define CHUNK(G)                                                              \
    { PHASE(0, G) PHASE(1, G) PHASE(2, G) PHASE(3, G)                         \
      PHASE(4, G) PHASE(5, G) PHASE(6, G) }

    // 10 chunks x 7 phases = 70 rows of pipeline per band.
    // Steady (guard-free) chunks: top band c=1..7, bottom band c=1..8;
    // in-band proof: top r=7..55 -> o in [4,58] subset [0,64);
    //                bottom r=68..123 -> o in [65,126] subset [64,128).
    const int ug_end = (blockIdx.x == 0) ? 8 : 9;
#pragma unroll 1
    for (int c = 0; c < 10; ++c) {
        if (c >= 1 && c < ug_end) {
            CHUNK(0)
        } else {
            CHUNK(1)
        }
    }
#undef CHUNK
#undef PHASE
}

extern "C" void kernel_launch(void* const* d_in, const int* in_sizes, int n_in,
                              void* d_out, int out_size) {
    const float* x    = (const float*)d_in[0];   // (64, 64, 128, 128)
    const float* w    = (const float*)d_in[1];   // (64, 7, 7)
    const float* bias = (const float*)d_in[2];   // (1,)
    float* out = (float*)d_out;                  // (64, 128, 128)

    dim3 grid(HW / BAND, 64);                    // 2 x 64 = 128 CTAs, one wave
    conv7x7_r15<<<grid, NT>>>(x, w, bias, out);
}

// round 17
// speedup vs baseline: 1.0994x; 1.0994x over previous
#include <cuda_runtime.h>
#include <cstdint>

// 7x7 single-out-channel conv via mma.sync tf32 implicit GEMM.
// Round 17 (= R16 resubmit after infra failure): R11's proven compact body,
// split into 256-thread CTAs (8 m-tiles x ONE k-half) -> 2 independent CTAs
// per SM, so per-row barriers of one CTA overlap with the other CTA's
// load/mma stream. k-half partials combine via atomicAdd into pre-zeroed
// output. grid (2 bands x 2 khalves, 64 imgs) = 256 CTAs, one wave.

#define HW 128
#define HW2 (HW * HW)
#define C_DIM 64
#define BAND 64
#define NT 256

static __device__ __forceinline__ uint32_t f2tf(float v) {
    uint32_t r;
    asm("cvt.rna.tf32.f32 %0, %1;" : "=r"(r) : "f"(v));
    return r;
}

static __device__ __forceinline__ void mma8(float (&d)[4], const uint32_t (&a)[4],
                                            uint32_t b0, uint32_t b1) {
    asm("mma.sync.aligned.m16n8k8.row.col.f32.tf32.tf32.f32 "
        "{%0,%1,%2,%3}, {%4,%5,%6,%7}, {%8,%9}, {%0,%1,%2,%3};"
        : "+f"(d[0]), "+f"(d[1]), "+f"(d[2]), "+f"(d[3])
        : "r"(a[0]), "r"(a[1]), "r"(a[2]), "r"(a[3]), "r"(b0), "r"(b1));
}

__global__ void zero_out_kernel(float4* __restrict__ o) {
    const size_t i = (size_t)blockIdx.x * 256 + threadIdx.x;
    o[i] = make_float4(0.f, 0.f, 0.f, 0.f);
}

__global__ void __launch_bounds__(NT, 2)
conv7x7_r17(const float* __restrict__ x, const float* __restrict__ w,
            const float* __restrict__ bias, float* __restrict__ out)
{
    // partial D for this CTA's k-half: [buffer][pixel][dw, pitch 10]
    __shared__ __align__(16) float s_part[2][HW][10];

    const int tid  = threadIdx.x;
    const int wid  = tid >> 5;        // 0..7: m-tile
    const int lane = tid & 31;
    const int g    = lane >> 2;       // pixel-within-tile row / n-index
    const int q    = lane & 3;        // k-quad
    const int pb   = wid * 16 + g;    // thread's pixel rows: pb, pb+8

    const int band = blockIdx.x & 1;
    const int kpb  = blockIdx.x >> 1; // k-half: channels kpb*32 .. kpb*32+31
    const int b    = blockIdx.y;

    const int ostart = band * BAND;
    const int oend   = ostart + BAND;
    const int rlo    = (ostart - 3 < 0) ? 0 : ostart - 3;
    const int rhi    = (oend + 2 > HW - 1) ? HW - 1 : oend + 2;

    // ---- B fragments resident in registers (this k-half only) ----
    uint32_t bw[7][4][2];
#pragma unroll
    for (int dh = 0; dh < 7; ++dh)
#pragma unroll
        for (int i = 0; i < 4; ++i) {
            const int c = (kpb * 4 + i) * 8 + 2 * q;
            bw[dh][i][0] = (g < 7) ? f2tf(w[c * 49 + dh * 7 + g]) : 0u;
            bw[dh][i][1] = (g < 7) ? f2tf(w[(c + 1) * 49 + dh * 7 + g]) : 0u;
        }

    float* outb = out + (size_t)b * HW2;
    const float badd = (kpb == 0) ? bias[0] : 0.f;

    float acc[7][4];
#pragma unroll
    for (int j = 0; j < 7; ++j)
#pragma unroll
        for (int k2 = 0; k2 < 4; ++k2) acc[j][k2] = 0.f;

    // single A pointer; k-step blocks reached via immediate offsets
    const float* pA = x + (size_t)b * C_DIM * HW2
                        + (size_t)(kpb * 32 + 2 * q) * HW2 + pb + (size_t)rlo * HW;

    uint32_t av[4][4];
#pragma unroll
    for (int i = 0; i < 4; ++i) {
        const float* p = pA + i * 8 * HW2;
        av[i][0] = __float_as_uint(p[0]);
        av[i][1] = __float_as_uint(p[8]);
        av[i][2] = __float_as_uint(p[HW2]);
        av[i][3] = __float_as_uint(p[HW2 + 8]);
    }
    pA += HW;   // points at row rlo+1

    int epar = 0;
    int r = rlo;

#define PHASE(P)                                                              \
    {                                                                         \
        if (r <= rhi) {                                                       \
            _Pragma("unroll") for (int i_ = 0; i_ < 4; ++i_) {                \
                uint32_t tmp_[4];                                             \
                _Pragma("unroll") for (int k_ = 0; k_ < 4; ++k_)              \
                    tmp_[k_] = f2tf(__uint_as_float(av[i_][k_]));             \
                if (r < rhi) {                                                \
                    const float* p_ = pA + i_ * 8 * HW2;                      \
                    av[i_][0] = __float_as_uint(p_[0]);                       \
                    av[i_][1] = __float_as_uint(p_[8]);                       \
                    av[i_][2] = __float_as_uint(p_[HW2]);                     \
                    av[i_][3] = __float_as_uint(p_[HW2 + 8]);                 \
                }                                                             \
                _Pragma("unroll") for (int j_ = 0; j_ < 7; ++j_) {            \
                    const int o_ = r - 3 + j_;                                \
                    if (o_ >= ostart && o_ < oend)                            \
                        mma8(acc[((P) + j_) % 7], tmp_,                       \
                             bw[6 - j_][i_][0], bw[6 - j_][i_][1]);           \
                }                                                             \
            }                                                                 \
            pA += HW;                                                         \
        }                                                                     \
        const int o0_ = r - 3;                                                \
        if (o0_ >= ostart && o0_ < oend) {                                    \
            float (&A_)[4] = acc[(P) % 7];                                    \
            *reinterpret_cast<float2*>(&s_part[epar][pb][2 * q]) =            \
                make_float2(A_[0], A_[1]);                                    \
            *reinterpret_cast<float2*>(&s_part[epar][pb + 8][2 * q]) =        \
                make_float2(A_[2], A_[3]);                                    \
            __syncthreads();                                                  \
            if (tid < HW) {                                                   \
                float s_ = badd;                                              \
                _Pragma("unroll") for (int dw_ = 0; dw_ < 7; ++dw_) {         \
                    const int p_ = tid + dw_ - 3;                             \
                    if ((unsigned)p_ < (unsigned)HW)                          \
                        s_ += s_part[epar][p_][dw_];                          \
                }                                                             \
                atomicAdd(outb + o0_ * HW + tid, s_);                         \
            }                                                                 \
            _Pragma("unroll") for (int k_ = 0; k_ < 4; ++k_)                  \
                A_[k_] = 0.f;                                                 \
            epar ^= 1;                                                        \
        }                                                                     \
        ++r;                                                                  \
    }

    // 70 phases (10 x 7) cover rlo..rhi for either band; guards retire
    // out-of-range work, tail outputs emitted in the same stream.
#pragma unroll 1
    for (int c = 0; c < 10; ++c) {
        PHASE(0) PHASE(1) PHASE(2) PHASE(3) PHASE(4) PHASE(5) PHASE(6)
    }
#undef PHASE
}

extern "C" void kernel_launch(void* const* d_in, const int* in_sizes, int n_in,
                              void* d_out, int out_size) {
    const float* x    = (const float*)d_in[0];   // (64, 64, 128, 128)
    const float* w    = (const float*)d_in[1];   // (64, 7, 7)
    const float* bias = (const float*)d_in[2];   // (1,)
    float* out = (float*)d_out;                  // (64, 128, 128)

    // zero the output (atomicAdd target); 64*128*128 floats = 256K float4
    zero_out_kernel<<<1024, 256>>>((float4*)out);

    dim3 grid(4, 64);   // (2 bands x 2 k-halves) x 64 images = 256 CTAs
    conv7x7_r17<<<grid, NT>>>(x, w, bias, out);
}